// round 15
// baseline (speedup 1.0000x reference)
#include <cuda_runtime.h>
#include <cuda_fp16.h>

#define B 64
#define E 100000
#define C 80000
#define NNZ 1600000
#define NGROUPS 10000
#define GEPS 1e-5f
#define CAP 48

// __device__ scratch (allocation-free rule). Feature-major layouts [feat][B].
// Invariant: g_cnt_* are ZERO on entry (zero-init .bss; gather kernels reset
// after reading) -> no zeroing pass, place has no dependence on transpose.
__device__ __align__(16) __half g_xTh[(size_t)E * B];        // 12.8 MB
__device__ __align__(16) __half g_hTh[(size_t)C * B];        // 10.2 MB
__device__ int g_cnt_c[C];
__device__ int g_cnt_e[E];
__device__ __align__(16) int2 g_ell_c[(size_t)C * CAP];      // 30.7 MB
__device__ __align__(16) int2 g_ell_e[(size_t)E * CAP];      // 38.4 MB

// ---------------------------------------------------------------------------
// transpose x [B,E] -> g_xTh [E,B] (fp16).
// ---------------------------------------------------------------------------
__global__ void k_transpose_in(const float* __restrict__ x) {
    __shared__ float tile[32][65];          // [e_local][b]
    int e0 = blockIdx.x * 32;
    int tx = threadIdx.x, ty = threadIdx.y; // (32,8)

    #pragma unroll
    for (int b = ty; b < 64; b += 8)
        tile[tx][b] = x[(size_t)b * E + e0 + tx];   // coalesced over e
    __syncthreads();

    __half2* dst = reinterpret_cast<__half2*>(g_xTh);
    #pragma unroll
    for (int i = 0; i < 32; i += 8) {
        int e = e0 + ty + i;
        float lo = tile[ty + i][2 * tx + 0];
        float hi = tile[ty + i][2 * tx + 1];
        dst[(size_t)e * 32 + tx] = __floats2half2_rn(lo, hi);
    }
}

// ---------------------------------------------------------------------------
// ELL build, both layers in one pass. Stores (row*128 byte-offset, bits(val)).
// ---------------------------------------------------------------------------
__global__ void k_place_both(const int* __restrict__ rows1,
                             const int* __restrict__ cols1,
                             const float* __restrict__ vals1,
                             const int* __restrict__ rows2,
                             const int* __restrict__ cols2,
                             const float* __restrict__ vals2) {
    int i = blockIdx.x * blockDim.x + threadIdx.x;
    if (i >= NNZ) return;
    int c1 = cols1[i], r1 = rows1[i];
    int c2 = cols2[i], r2 = rows2[i];
    float v1 = vals1[i], v2 = vals2[i];
    int p1 = atomicAdd(&g_cnt_c[c1], 1);
    int p2 = atomicAdd(&g_cnt_e[c2], 1);
    if (p1 < CAP)
        g_ell_c[(size_t)c1 * CAP + p1] = make_int2(r1 * 128, __float_as_int(v1));
    if (p2 < CAP)
        g_ell_e[(size_t)c2 * CAP + p2] = make_int2(r2 * 128, __float_as_int(v2));
}

// ---------------------------------------------------------------------------
// Gather core (R6-proven v2): warp = one output feature. Lane q=lane&15 owns
// a batch quad (8B fp16); half=lane>>4 splits the nnz list. LDG.64 by 16 lanes
// covers one 128B row -> warp retires 2 nnz per load round; x2 unroll per half.
// fp32 accumulation; returns per-half float4, caller shfl-combines.
// ---------------------------------------------------------------------------
__device__ __forceinline__ float4 warp_gather_q(const int2* __restrict__ pr, int n,
                                                int2* spair, int lane,
                                                const char* __restrict__ src_base) {
    for (int j = lane; j < n; j += 32) spair[j] = __ldg(&pr[j]);
    __syncwarp();

    int q = lane & 15, half = lane >> 4;
    const char* src = src_base + q * 8;     // quad's 8B within each 128B row
    float4 a0 = {0.f, 0.f, 0.f, 0.f};
    float4 a1 = {0.f, 0.f, 0.f, 0.f};
    int j = half;
    for (; j + 2 < n; j += 4) {             // this half: j and j+2
        int2 p0 = spair[j];
        int2 p1 = spair[j + 2];
        float2 r0 = *reinterpret_cast<const float2*>(src + p0.x);
        float2 r1 = *reinterpret_cast<const float2*>(src + p1.x);
        float v0 = __int_as_float(p0.y);
        float v1 = __int_as_float(p1.y);
        float2 x00 = __half22float2(*reinterpret_cast<const __half2*>(&r0.x));
        float2 x01 = __half22float2(*reinterpret_cast<const __half2*>(&r0.y));
        float2 x10 = __half22float2(*reinterpret_cast<const __half2*>(&r1.x));
        float2 x11 = __half22float2(*reinterpret_cast<const __half2*>(&r1.y));
        a0.x += x00.x * v0; a0.y += x00.y * v0;
        a0.z += x01.x * v0; a0.w += x01.y * v0;
        a1.x += x10.x * v1; a1.y += x10.y * v1;
        a1.z += x11.x * v1; a1.w += x11.y * v1;
    }
    if (j < n) {
        int2 p = spair[j];
        float2 r = *reinterpret_cast<const float2*>(src + p.x);
        float v = __int_as_float(p.y);
        float2 xa = __half22float2(*reinterpret_cast<const __half2*>(&r.x));
        float2 xb = __half22float2(*reinterpret_cast<const __half2*>(&r.y));
        a0.x += xa.x * v; a0.y += xa.y * v;
        a0.z += xb.x * v; a0.w += xb.y * v;
    }
    float4 acc;
    acc.x = a0.x + a1.x; acc.y = a0.y + a1.y;
    acc.z = a0.z + a1.z; acc.w = a0.w + a1.w;
    return acc;
}

__device__ __forceinline__ float4 combine_halves(float4 acc) {
    acc.x += __shfl_xor_sync(0xffffffffu, acc.x, 16);
    acc.y += __shfl_xor_sync(0xffffffffu, acc.y, 16);
    acc.z += __shfl_xor_sync(0xffffffffu, acc.z, 16);
    acc.w += __shfl_xor_sync(0xffffffffu, acc.w, 16);
    return acc;
}

// ---------------------------------------------------------------------------
// gather_in fused with GroupLayerNorm + ELU. Block = 1 group = 8 channels.
// Reads + RESETS g_cnt_c (maintains zero-on-entry invariant).
// ---------------------------------------------------------------------------
__global__ void k_gather_in_norm(const float* __restrict__ b_in,
                                 const float* __restrict__ gamma,
                                 const float* __restrict__ beta) {
    __shared__ __align__(16) int2 spair[8][CAP];    // 3 KB
    __shared__ float sh[8][64];
    __shared__ float s_mean[64], s_inv[64];
    int g = blockIdx.x;
    int w = threadIdx.x >> 5;
    int lane = threadIdx.x & 31;
    int q = lane & 15, half = lane >> 4;
    int c = g * 8 + w;

    int n_raw = 0;
    if (lane == 0) {
        n_raw = g_cnt_c[c];
        g_cnt_c[c] = 0;                    // reset for next launch
    }
    n_raw = __shfl_sync(0xffffffffu, n_raw, 0);
    int n = min(n_raw, CAP);

    float4 acc = warp_gather_q(&g_ell_c[(size_t)c * CAP], n, spair[w], lane,
                               reinterpret_cast<const char*>(g_xTh));
    acc = combine_halves(acc);
    if (half == 0) {
        float bi = b_in[c];
        sh[w][4 * q + 0] = acc.x + bi;
        sh[w][4 * q + 1] = acc.y + bi;
        sh[w][4 * q + 2] = acc.z + bi;
        sh[w][4 * q + 3] = acc.w + bi;
    }
    __syncthreads();

    if (threadIdx.x < 64) {
        int b = threadIdx.x;
        float s = 0.f, ss = 0.f;
        #pragma unroll
        for (int r = 0; r < 8; r++) {
            float h = sh[r][b];
            s += h; ss += h * h;
        }
        float mean = s * 0.125f;
        float var = ss * 0.125f - mean * mean;
        s_mean[b] = mean;
        s_inv[b] = rsqrtf(var + GEPS);
    }
    __syncthreads();

    // normalize + affine + ELU -> half2. Thread t: r = t>>5, batch pair bp = t&31.
    {
        int r = threadIdx.x >> 5;
        int bp = threadIdx.x & 31;
        int b0 = 2 * bp, b1 = 2 * bp + 1;
        float ga = gamma[g * 8 + r], be = beta[g * 8 + r];
        float y0 = ga * ((sh[r][b0] - s_mean[b0]) * s_inv[b0]) + be;
        float y1 = ga * ((sh[r][b1] - s_mean[b1]) * s_inv[b1]) + be;
        y0 = (y0 > 0.f) ? y0 : (__expf(y0) - 1.f);
        y1 = (y1 > 0.f) ? y1 : (__expf(y1) - 1.f);
        reinterpret_cast<__half2*>(g_hTh)[(size_t)(g * 8 + r) * 32 + bp] =
            __floats2half2_rn(y0, y1);
    }
}

// ---------------------------------------------------------------------------
// gather_out + bias + residual(fp32 x) + fused transpose to out[b][e].
// Block = 8 consecutive edges. Reads + RESETS g_cnt_e.
// ---------------------------------------------------------------------------
__global__ void k_gather_out(const float* __restrict__ x,
                             const float* __restrict__ b_out,
                             float* __restrict__ out) {
    __shared__ __align__(16) int2 spair[8][CAP];
    __shared__ float sh[8][68];             // padded
    int e0 = blockIdx.x * 8;
    int w = threadIdx.x >> 5;
    int lane = threadIdx.x & 31;
    int q = lane & 15, half = lane >> 4;
    int e = e0 + w;

    int n_raw = 0;
    if (lane == 0) {
        n_raw = g_cnt_e[e];
        g_cnt_e[e] = 0;                    // reset for next launch
    }
    n_raw = __shfl_sync(0xffffffffu, n_raw, 0);
    int n = min(n_raw, CAP);

    float4 acc = warp_gather_q(&g_ell_e[(size_t)e * CAP], n, spair[w], lane,
                               reinterpret_cast<const char*>(g_hTh));
    acc = combine_halves(acc);
    if (half == 0) {
        float bo = b_out[e];
        sh[w][4 * q + 0] = acc.x + bo;
        sh[w][4 * q + 1] = acc.y + bo;
        sh[w][4 * q + 2] = acc.z + bo;
        sh[w][4 * q + 3] = acc.w + bo;
    }
    __syncthreads();

    // write phase: thread t -> b = t>>2, e_local = (t&3)*2; float2 per thread.
    int b = threadIdx.x >> 2;
    int el = (threadIdx.x & 3) * 2;
    size_t gidx = (size_t)b * E + e0 + el;
    float2 xv = *reinterpret_cast<const float2*>(&x[gidx]);
    float2 o;
    o.x = sh[el + 0][b] + xv.x;
    o.y = sh[el + 1][b] + xv.y;
    *reinterpret_cast<float2*>(&out[gidx]) = o;
}

// ---------------------------------------------------------------------------
// inputs: 0:x 1:v_in 2:b_in 3:v_out 4:b_out 5:gamma 6:beta
// 7:w_in_rows 8:w_in_cols 9:w_out_rows 10:w_out_cols 11:channel_groups(unused)
// Fork: place (atomic-bound) runs on a side stream concurrently with the
// transpose (DRAM-bound); event join before gather_in. Standard capture-
// compatible fork/join; stream/events created lazily on the first
// (non-captured) correctness call and reused thereafter.
// ---------------------------------------------------------------------------
extern "C" void kernel_launch(void* const* d_in, const int* in_sizes, int n_in,
                              void* d_out, int out_size) {
    const float* x      = (const float*)d_in[0];
    const float* v_in   = (const float*)d_in[1];
    const float* b_in   = (const float*)d_in[2];
    const float* v_out  = (const float*)d_in[3];
    const float* b_out  = (const float*)d_in[4];
    const float* gamma  = (const float*)d_in[5];
    const float* beta   = (const float*)d_in[6];
    const int* w_in_rows  = (const int*)d_in[7];
    const int* w_in_cols  = (const int*)d_in[8];
    const int* w_out_rows = (const int*)d_in[9];
    const int* w_out_cols = (const int*)d_in[10];
    float* out = (float*)d_out;

    static cudaStream_t s2 = nullptr;
    static cudaEvent_t ev_fork = nullptr, ev_join = nullptr;
    if (s2 == nullptr) {
        cudaStreamCreateWithFlags(&s2, cudaStreamNonBlocking);
        cudaEventCreateWithFlags(&ev_fork, cudaEventDisableTiming);
        cudaEventCreateWithFlags(&ev_join, cudaEventDisableTiming);
    }

    dim3 tb(32, 8);

    cudaEventRecord(ev_fork, 0);
    cudaStreamWaitEvent(s2, ev_fork, 0);
    k_place_both<<<(NNZ + 255) / 256, 256, 0, s2>>>(w_in_rows, w_in_cols, v_in,
                                                    w_out_rows, w_out_cols, v_out);
    cudaEventRecord(ev_join, s2);

    k_transpose_in<<<E / 32, tb>>>(x);

    cudaStreamWaitEvent(0, ev_join, 0);
    k_gather_in_norm<<<NGROUPS, 256>>>(b_in, gamma, beta);
    k_gather_out<<<E / 8, 256>>>(x, b_out, out);
}

// round 16
// speedup vs baseline: 3.7400x; 3.7400x over previous
#include <cuda_runtime.h>
#include <cuda_fp16.h>

#define B 64
#define E 100000
#define C 80000
#define NNZ 1600000
#define NGROUPS 10000
#define GEPS 1e-5f
#define CAP 48

// __device__ scratch (allocation-free rule). Feature-major layouts [feat][B].
__device__ __align__(16) __half g_xTh[(size_t)E * B];        // 12.8 MB
__device__ __align__(16) __half g_hTh[(size_t)C * B];        // 10.2 MB
__device__ int g_cnt_c[C];
__device__ int g_cnt_e[E];
__device__ __align__(16) int2 g_ell_c[(size_t)C * CAP];      // 30.7 MB
__device__ __align__(16) int2 g_ell_e[(size_t)E * CAP];      // 38.4 MB

// ---------------------------------------------------------------------------
// zero both counter arrays (cheap, runs before the fork).
// ---------------------------------------------------------------------------
__global__ void k_zero_both() {
    int i = blockIdx.x * blockDim.x + threadIdx.x;
    if (i < C) g_cnt_c[i] = 0;
    if (i < E) g_cnt_e[i] = 0;
}

// ---------------------------------------------------------------------------
// transpose x [B,E] -> g_xTh [E,B] (fp16).
// ---------------------------------------------------------------------------
__global__ void k_transpose_in(const float* __restrict__ x) {
    __shared__ float tile[32][65];          // [e_local][b]
    int e0 = blockIdx.x * 32;
    int tx = threadIdx.x, ty = threadIdx.y; // (32,8)

    #pragma unroll
    for (int b = ty; b < 64; b += 8)
        tile[tx][b] = x[(size_t)b * E + e0 + tx];   // coalesced over e
    __syncthreads();

    __half2* dst = reinterpret_cast<__half2*>(g_xTh);
    #pragma unroll
    for (int i = 0; i < 32; i += 8) {
        int e = e0 + ty + i;
        float lo = tile[ty + i][2 * tx + 0];
        float hi = tile[ty + i][2 * tx + 1];
        dst[(size_t)e * 32 + tx] = __floats2half2_rn(lo, hi);
    }
}

// ---------------------------------------------------------------------------
// ELL build, both layers in one pass. Stores (row*128 byte-offset, bits(val)).
// ---------------------------------------------------------------------------
__global__ void k_place_both(const int* __restrict__ rows1,
                             const int* __restrict__ cols1,
                             const float* __restrict__ vals1,
                             const int* __restrict__ rows2,
                             const int* __restrict__ cols2,
                             const float* __restrict__ vals2) {
    int i = blockIdx.x * blockDim.x + threadIdx.x;
    if (i >= NNZ) return;
    int c1 = cols1[i], r1 = rows1[i];
    int c2 = cols2[i], r2 = rows2[i];
    float v1 = vals1[i], v2 = vals2[i];
    int p1 = atomicAdd(&g_cnt_c[c1], 1);
    int p2 = atomicAdd(&g_cnt_e[c2], 1);
    if (p1 < CAP)
        g_ell_c[(size_t)c1 * CAP + p1] = make_int2(r1 * 128, __float_as_int(v1));
    if (p2 < CAP)
        g_ell_e[(size_t)c2 * CAP + p2] = make_int2(r2 * 128, __float_as_int(v2));
}

// ---------------------------------------------------------------------------
// Gather core (R6-proven v2): warp = one output feature. Lane q=lane&15 owns
// a batch quad (8B fp16); half=lane>>4 splits the nnz list. LDG.64 by 16 lanes
// covers one 128B row -> warp retires 2 nnz per load round; x2 unroll per half.
// fp32 accumulation; returns per-half float4, caller shfl-combines.
// ---------------------------------------------------------------------------
__device__ __forceinline__ float4 warp_gather_q(const int2* __restrict__ pr, int n,
                                                int2* spair, int lane,
                                                const char* __restrict__ src_base) {
    for (int j = lane; j < n; j += 32) spair[j] = __ldg(&pr[j]);
    __syncwarp();

    int q = lane & 15, half = lane >> 4;
    const char* src = src_base + q * 8;     // quad's 8B within each 128B row
    float4 a0 = {0.f, 0.f, 0.f, 0.f};
    float4 a1 = {0.f, 0.f, 0.f, 0.f};
    int j = half;
    for (; j + 2 < n; j += 4) {             // this half: j and j+2
        int2 p0 = spair[j];
        int2 p1 = spair[j + 2];
        float2 r0 = *reinterpret_cast<const float2*>(src + p0.x);
        float2 r1 = *reinterpret_cast<const float2*>(src + p1.x);
        float v0 = __int_as_float(p0.y);
        float v1 = __int_as_float(p1.y);
        float2 x00 = __half22float2(*reinterpret_cast<const __half2*>(&r0.x));
        float2 x01 = __half22float2(*reinterpret_cast<const __half2*>(&r0.y));
        float2 x10 = __half22float2(*reinterpret_cast<const __half2*>(&r1.x));
        float2 x11 = __half22float2(*reinterpret_cast<const __half2*>(&r1.y));
        a0.x += x00.x * v0; a0.y += x00.y * v0;
        a0.z += x01.x * v0; a0.w += x01.y * v0;
        a1.x += x10.x * v1; a1.y += x10.y * v1;
        a1.z += x11.x * v1; a1.w += x11.y * v1;
    }
    if (j < n) {
        int2 p = spair[j];
        float2 r = *reinterpret_cast<const float2*>(src + p.x);
        float v = __int_as_float(p.y);
        float2 xa = __half22float2(*reinterpret_cast<const __half2*>(&r.x));
        float2 xb = __half22float2(*reinterpret_cast<const __half2*>(&r.y));
        a0.x += xa.x * v; a0.y += xa.y * v;
        a0.z += xb.x * v; a0.w += xb.y * v;
    }
    float4 acc;
    acc.x = a0.x + a1.x; acc.y = a0.y + a1.y;
    acc.z = a0.z + a1.z; acc.w = a0.w + a1.w;
    return acc;
}

__device__ __forceinline__ float4 combine_halves(float4 acc) {
    acc.x += __shfl_xor_sync(0xffffffffu, acc.x, 16);
    acc.y += __shfl_xor_sync(0xffffffffu, acc.y, 16);
    acc.z += __shfl_xor_sync(0xffffffffu, acc.z, 16);
    acc.w += __shfl_xor_sync(0xffffffffu, acc.w, 16);
    return acc;
}

// ---------------------------------------------------------------------------
// gather_in fused with GroupLayerNorm + ELU. Block = 1 group = 8 channels.
// Counters are READ-ONLY here (reset path proved pathological in R8/R15).
// ---------------------------------------------------------------------------
__global__ void k_gather_in_norm(const float* __restrict__ b_in,
                                 const float* __restrict__ gamma,
                                 const float* __restrict__ beta) {
    __shared__ __align__(16) int2 spair[8][CAP];    // 3 KB
    __shared__ float sh[8][64];
    __shared__ float s_mean[64], s_inv[64];
    int g = blockIdx.x;
    int w = threadIdx.x >> 5;
    int lane = threadIdx.x & 31;
    int q = lane & 15, half = lane >> 4;
    int c = g * 8 + w;

    int n = min(g_cnt_c[c], CAP);
    float4 acc = warp_gather_q(&g_ell_c[(size_t)c * CAP], n, spair[w], lane,
                               reinterpret_cast<const char*>(g_xTh));
    acc = combine_halves(acc);
    if (half == 0) {
        float bi = b_in[c];
        sh[w][4 * q + 0] = acc.x + bi;
        sh[w][4 * q + 1] = acc.y + bi;
        sh[w][4 * q + 2] = acc.z + bi;
        sh[w][4 * q + 3] = acc.w + bi;
    }
    __syncthreads();

    if (threadIdx.x < 64) {
        int b = threadIdx.x;
        float s = 0.f, ss = 0.f;
        #pragma unroll
        for (int r = 0; r < 8; r++) {
            float h = sh[r][b];
            s += h; ss += h * h;
        }
        float mean = s * 0.125f;
        float var = ss * 0.125f - mean * mean;
        s_mean[b] = mean;
        s_inv[b] = rsqrtf(var + GEPS);
    }
    __syncthreads();

    // normalize + affine + ELU -> half2. Thread t: r = t>>5, batch pair bp = t&31.
    {
        int r = threadIdx.x >> 5;
        int bp = threadIdx.x & 31;
        int b0 = 2 * bp, b1 = 2 * bp + 1;
        float ga = gamma[g * 8 + r], be = beta[g * 8 + r];
        float y0 = ga * ((sh[r][b0] - s_mean[b0]) * s_inv[b0]) + be;
        float y1 = ga * ((sh[r][b1] - s_mean[b1]) * s_inv[b1]) + be;
        y0 = (y0 > 0.f) ? y0 : (__expf(y0) - 1.f);
        y1 = (y1 > 0.f) ? y1 : (__expf(y1) - 1.f);
        reinterpret_cast<__half2*>(g_hTh)[(size_t)(g * 8 + r) * 32 + bp] =
            __floats2half2_rn(y0, y1);
    }
}

// ---------------------------------------------------------------------------
// gather_out + bias + residual(fp32 x) + fused transpose to out[b][e].
// Block = 8 consecutive edges. Counters READ-ONLY.
// ---------------------------------------------------------------------------
__global__ void k_gather_out(const float* __restrict__ x,
                             const float* __restrict__ b_out,
                             float* __restrict__ out) {
    __shared__ __align__(16) int2 spair[8][CAP];
    __shared__ float sh[8][68];             // padded
    int e0 = blockIdx.x * 8;
    int w = threadIdx.x >> 5;
    int lane = threadIdx.x & 31;
    int q = lane & 15, half = lane >> 4;
    int e = e0 + w;

    int n = min(g_cnt_e[e], CAP);
    float4 acc = warp_gather_q(&g_ell_e[(size_t)e * CAP], n, spair[w], lane,
                               reinterpret_cast<const char*>(g_hTh));
    acc = combine_halves(acc);
    if (half == 0) {
        float bo = b_out[e];
        sh[w][4 * q + 0] = acc.x + bo;
        sh[w][4 * q + 1] = acc.y + bo;
        sh[w][4 * q + 2] = acc.z + bo;
        sh[w][4 * q + 3] = acc.w + bo;
    }
    __syncthreads();

    // write phase: thread t -> b = t>>2, e_local = (t&3)*2; float2 per thread.
    int b = threadIdx.x >> 2;
    int el = (threadIdx.x & 3) * 2;
    size_t gidx = (size_t)b * E + e0 + el;
    float2 xv = *reinterpret_cast<const float2*>(&x[gidx]);
    float2 o;
    o.x = sh[el + 0][b] + xv.x;
    o.y = sh[el + 1][b] + xv.y;
    *reinterpret_cast<float2*>(&out[gidx]) = o;
}

// ---------------------------------------------------------------------------
// inputs: 0:x 1:v_in 2:b_in 3:v_out 4:b_out 5:gamma 6:beta
// 7:w_in_rows 8:w_in_cols 9:w_out_rows 10:w_out_cols 11:channel_groups(unused)
// Order: zero -> fork{ place (s2) || transpose (s0) } -> join -> gathers.
// ---------------------------------------------------------------------------
extern "C" void kernel_launch(void* const* d_in, const int* in_sizes, int n_in,
                              void* d_out, int out_size) {
    const float* x      = (const float*)d_in[0];
    const float* v_in   = (const float*)d_in[1];
    const float* b_in   = (const float*)d_in[2];
    const float* v_out  = (const float*)d_in[3];
    const float* b_out  = (const float*)d_in[4];
    const float* gamma  = (const float*)d_in[5];
    const float* beta   = (const float*)d_in[6];
    const int* w_in_rows  = (const int*)d_in[7];
    const int* w_in_cols  = (const int*)d_in[8];
    const int* w_out_rows = (const int*)d_in[9];
    const int* w_out_cols = (const int*)d_in[10];
    float* out = (float*)d_out;

    static cudaStream_t s2 = nullptr;
    static cudaEvent_t ev_fork = nullptr, ev_join = nullptr;
    if (s2 == nullptr) {
        cudaStreamCreateWithFlags(&s2, cudaStreamNonBlocking);
        cudaEventCreateWithFlags(&ev_fork, cudaEventDisableTiming);
        cudaEventCreateWithFlags(&ev_join, cudaEventDisableTiming);
    }

    dim3 tb(32, 8);

    k_zero_both<<<(E + 255) / 256, 256>>>();

    cudaEventRecord(ev_fork, 0);
    cudaStreamWaitEvent(s2, ev_fork, 0);
    k_place_both<<<(NNZ + 255) / 256, 256, 0, s2>>>(w_in_rows, w_in_cols, v_in,
                                                    w_out_rows, w_out_cols, v_out);
    cudaEventRecord(ev_join, s2);

    k_transpose_in<<<E / 32, tb>>>(x);

    cudaStreamWaitEvent(0, ev_join, 0);
    k_gather_in_norm<<<NGROUPS, 256>>>(b_in, gamma, beta);
    k_gather_out<<<E / 8, 256>>>(x, b_out, out);
}

// round 17
// speedup vs baseline: 3.8012x; 1.0164x over previous
#include <cuda_runtime.h>
#include <cuda_fp16.h>

#define B 64
#define E 100000
#define C 80000
#define NNZ 1600000
#define NGROUPS 10000
#define GEPS 1e-5f
#define CAP 48

// __device__ scratch (allocation-free rule). Feature-major layouts [feat][B].
__device__ __align__(16) __half g_xTh[(size_t)E * B];        // 12.8 MB
__device__ __align__(16) __half g_hTh[(size_t)C * B];        // 10.2 MB
__device__ int g_cnt_c[C];
__device__ int g_cnt_e[E];
__device__ __align__(16) int2 g_ell_c[(size_t)C * CAP];      // 30.7 MB
__device__ __align__(16) int2 g_ell_e[(size_t)E * CAP];      // 38.4 MB

// ---------------------------------------------------------------------------
// zero both counter arrays.
// ---------------------------------------------------------------------------
__global__ void k_zero_both() {
    int i = blockIdx.x * blockDim.x + threadIdx.x;
    if (i < C) g_cnt_c[i] = 0;
    if (i < E) g_cnt_e[i] = 0;
}

// ---------------------------------------------------------------------------
// transpose x [B,E] -> g_xTh [E,B] (fp16).
// ---------------------------------------------------------------------------
__global__ void k_transpose_in(const float* __restrict__ x) {
    __shared__ float tile[32][65];          // [e_local][b]
    int e0 = blockIdx.x * 32;
    int tx = threadIdx.x, ty = threadIdx.y; // (32,8)

    #pragma unroll
    for (int b = ty; b < 64; b += 8)
        tile[tx][b] = x[(size_t)b * E + e0 + tx];   // coalesced over e
    __syncthreads();

    __half2* dst = reinterpret_cast<__half2*>(g_xTh);
    #pragma unroll
    for (int i = 0; i < 32; i += 8) {
        int e = e0 + ty + i;
        float lo = tile[ty + i][2 * tx + 0];
        float hi = tile[ty + i][2 * tx + 1];
        dst[(size_t)e * 32 + tx] = __floats2half2_rn(lo, hi);
    }
}

// ---------------------------------------------------------------------------
// ELL build, one layer per kernel (enables pipelining with the gathers).
// Stores (row*128 byte-offset, bits(val)).
// ---------------------------------------------------------------------------
__global__ void k_place_c(const int* __restrict__ rows,
                          const int* __restrict__ cols,
                          const float* __restrict__ vals) {
    int i = blockIdx.x * blockDim.x + threadIdx.x;
    if (i >= NNZ) return;
    int c = cols[i], r = rows[i];
    float v = vals[i];
    int p = atomicAdd(&g_cnt_c[c], 1);
    if (p < CAP)
        g_ell_c[(size_t)c * CAP + p] = make_int2(r * 128, __float_as_int(v));
}

__global__ void k_place_e(const int* __restrict__ rows,
                          const int* __restrict__ cols,
                          const float* __restrict__ vals) {
    int i = blockIdx.x * blockDim.x + threadIdx.x;
    if (i >= NNZ) return;
    int c = cols[i], r = rows[i];
    float v = vals[i];
    int p = atomicAdd(&g_cnt_e[c], 1);
    if (p < CAP)
        g_ell_e[(size_t)c * CAP + p] = make_int2(r * 128, __float_as_int(v));
}

// ---------------------------------------------------------------------------
// Gather core (R6-proven v2): warp = one output feature. Lane q=lane&15 owns
// a batch quad (8B fp16); half=lane>>4 splits the nnz list. LDG.64 by 16 lanes
// covers one 128B row -> warp retires 2 nnz per load round; x2 unroll per half.
// fp32 accumulation; returns per-half float4, caller shfl-combines.
// ---------------------------------------------------------------------------
__device__ __forceinline__ float4 warp_gather_q(const int2* __restrict__ pr, int n,
                                                int2* spair, int lane,
                                                const char* __restrict__ src_base) {
    for (int j = lane; j < n; j += 32) spair[j] = __ldg(&pr[j]);
    __syncwarp();

    int q = lane & 15, half = lane >> 4;
    const char* src = src_base + q * 8;     // quad's 8B within each 128B row
    float4 a0 = {0.f, 0.f, 0.f, 0.f};
    float4 a1 = {0.f, 0.f, 0.f, 0.f};
    int j = half;
    for (; j + 2 < n; j += 4) {             // this half: j and j+2
        int2 p0 = spair[j];
        int2 p1 = spair[j + 2];
        float2 r0 = *reinterpret_cast<const float2*>(src + p0.x);
        float2 r1 = *reinterpret_cast<const float2*>(src + p1.x);
        float v0 = __int_as_float(p0.y);
        float v1 = __int_as_float(p1.y);
        float2 x00 = __half22float2(*reinterpret_cast<const __half2*>(&r0.x));
        float2 x01 = __half22float2(*reinterpret_cast<const __half2*>(&r0.y));
        float2 x10 = __half22float2(*reinterpret_cast<const __half2*>(&r1.x));
        float2 x11 = __half22float2(*reinterpret_cast<const __half2*>(&r1.y));
        a0.x += x00.x * v0; a0.y += x00.y * v0;
        a0.z += x01.x * v0; a0.w += x01.y * v0;
        a1.x += x10.x * v1; a1.y += x10.y * v1;
        a1.z += x11.x * v1; a1.w += x11.y * v1;
    }
    if (j < n) {
        int2 p = spair[j];
        float2 r = *reinterpret_cast<const float2*>(src + p.x);
        float v = __int_as_float(p.y);
        float2 xa = __half22float2(*reinterpret_cast<const __half2*>(&r.x));
        float2 xb = __half22float2(*reinterpret_cast<const __half2*>(&r.y));
        a0.x += xa.x * v; a0.y += xa.y * v;
        a0.z += xb.x * v; a0.w += xb.y * v;
    }
    float4 acc;
    acc.x = a0.x + a1.x; acc.y = a0.y + a1.y;
    acc.z = a0.z + a1.z; acc.w = a0.w + a1.w;
    return acc;
}

__device__ __forceinline__ float4 combine_halves(float4 acc) {
    acc.x += __shfl_xor_sync(0xffffffffu, acc.x, 16);
    acc.y += __shfl_xor_sync(0xffffffffu, acc.y, 16);
    acc.z += __shfl_xor_sync(0xffffffffu, acc.z, 16);
    acc.w += __shfl_xor_sync(0xffffffffu, acc.w, 16);
    return acc;
}

// ---------------------------------------------------------------------------
// gather_in fused with GroupLayerNorm + ELU. Block = 1 group = 8 channels.
// Counters are READ-ONLY (reset-in-gather proved pathological in R8/R15).
// ---------------------------------------------------------------------------
__global__ void k_gather_in_norm(const float* __restrict__ b_in,
                                 const float* __restrict__ gamma,
                                 const float* __restrict__ beta) {
    __shared__ __align__(16) int2 spair[8][CAP];    // 3 KB
    __shared__ float sh[8][64];
    __shared__ float s_mean[64], s_inv[64];
    int g = blockIdx.x;
    int w = threadIdx.x >> 5;
    int lane = threadIdx.x & 31;
    int q = lane & 15, half = lane >> 4;
    int c = g * 8 + w;

    int n = min(g_cnt_c[c], CAP);
    float4 acc = warp_gather_q(&g_ell_c[(size_t)c * CAP], n, spair[w], lane,
                               reinterpret_cast<const char*>(g_xTh));
    acc = combine_halves(acc);
    if (half == 0) {
        float bi = b_in[c];
        sh[w][4 * q + 0] = acc.x + bi;
        sh[w][4 * q + 1] = acc.y + bi;
        sh[w][4 * q + 2] = acc.z + bi;
        sh[w][4 * q + 3] = acc.w + bi;
    }
    __syncthreads();

    if (threadIdx.x < 64) {
        int b = threadIdx.x;
        float s = 0.f, ss = 0.f;
        #pragma unroll
        for (int r = 0; r < 8; r++) {
            float h = sh[r][b];
            s += h; ss += h * h;
        }
        float mean = s * 0.125f;
        float var = ss * 0.125f - mean * mean;
        s_mean[b] = mean;
        s_inv[b] = rsqrtf(var + GEPS);
    }
    __syncthreads();

    // normalize + affine + ELU -> half2. Thread t: r = t>>5, batch pair bp = t&31.
    {
        int r = threadIdx.x >> 5;
        int bp = threadIdx.x & 31;
        int b0 = 2 * bp, b1 = 2 * bp + 1;
        float ga = gamma[g * 8 + r], be = beta[g * 8 + r];
        float y0 = ga * ((sh[r][b0] - s_mean[b0]) * s_inv[b0]) + be;
        float y1 = ga * ((sh[r][b1] - s_mean[b1]) * s_inv[b1]) + be;
        y0 = (y0 > 0.f) ? y0 : (__expf(y0) - 1.f);
        y1 = (y1 > 0.f) ? y1 : (__expf(y1) - 1.f);
        reinterpret_cast<__half2*>(g_hTh)[(size_t)(g * 8 + r) * 32 + bp] =
            __floats2half2_rn(y0, y1);
    }
}

// ---------------------------------------------------------------------------
// gather_out + bias + residual(fp32 x) + fused transpose to out[b][e].
// Block = 8 consecutive edges. Counters READ-ONLY.
// ---------------------------------------------------------------------------
__global__ void k_gather_out(const float* __restrict__ x,
                             const float* __restrict__ b_out,
                             float* __restrict__ out) {
    __shared__ __align__(16) int2 spair[8][CAP];
    __shared__ float sh[8][68];             // padded
    int e0 = blockIdx.x * 8;
    int w = threadIdx.x >> 5;
    int lane = threadIdx.x & 31;
    int q = lane & 15, half = lane >> 4;
    int e = e0 + w;

    int n = min(g_cnt_e[e], CAP);
    float4 acc = warp_gather_q(&g_ell_e[(size_t)e * CAP], n, spair[w], lane,
                               reinterpret_cast<const char*>(g_hTh));
    acc = combine_halves(acc);
    if (half == 0) {
        float bo = b_out[e];
        sh[w][4 * q + 0] = acc.x + bo;
        sh[w][4 * q + 1] = acc.y + bo;
        sh[w][4 * q + 2] = acc.z + bo;
        sh[w][4 * q + 3] = acc.w + bo;
    }
    __syncthreads();

    // write phase: thread t -> b = t>>2, e_local = (t&3)*2; float2 per thread.
    int b = threadIdx.x >> 2;
    int el = (threadIdx.x & 3) * 2;
    size_t gidx = (size_t)b * E + e0 + el;
    float2 xv = *reinterpret_cast<const float2*>(&x[gidx]);
    float2 o;
    o.x = sh[el + 0][b] + xv.x;
    o.y = sh[el + 1][b] + xv.y;
    *reinterpret_cast<float2*>(&out[gidx]) = o;
}

// ---------------------------------------------------------------------------
// inputs: 0:x 1:v_in 2:b_in 3:v_out 4:b_out 5:gamma 6:beta
// 7:w_in_rows 8:w_in_cols 9:w_out_rows 10:w_out_cols 11:channel_groups(unused)
//
// Pipeline (s0 = capture stream, s2 = side stream):
//   s0: zero ─ place_c ───────────── gather_in ── gather_out
//   s2: transpose ──(after zero)── place_e ─────────┘
// gather_in waits on transpose (evT); gather_out waits on place_e (evE).
// ---------------------------------------------------------------------------
extern "C" void kernel_launch(void* const* d_in, const int* in_sizes, int n_in,
                              void* d_out, int out_size) {
    const float* x      = (const float*)d_in[0];
    const float* v_in   = (const float*)d_in[1];
    const float* b_in   = (const float*)d_in[2];
    const float* v_out  = (const float*)d_in[3];
    const float* b_out  = (const float*)d_in[4];
    const float* gamma  = (const float*)d_in[5];
    const float* beta   = (const float*)d_in[6];
    const int* w_in_rows  = (const int*)d_in[7];
    const int* w_in_cols  = (const int*)d_in[8];
    const int* w_out_rows = (const int*)d_in[9];
    const int* w_out_cols = (const int*)d_in[10];
    float* out = (float*)d_out;

    static cudaStream_t s2 = nullptr;
    static cudaEvent_t evF = nullptr, evZ = nullptr, evT = nullptr, evE = nullptr;
    if (s2 == nullptr) {
        cudaStreamCreateWithFlags(&s2, cudaStreamNonBlocking);
        cudaEventCreateWithFlags(&evF, cudaEventDisableTiming);
        cudaEventCreateWithFlags(&evZ, cudaEventDisableTiming);
        cudaEventCreateWithFlags(&evT, cudaEventDisableTiming);
        cudaEventCreateWithFlags(&evE, cudaEventDisableTiming);
    }

    dim3 tb(32, 8);

    // fork s2 from the capture stream
    cudaEventRecord(evF, 0);
    cudaStreamWaitEvent(s2, evF, 0);

    // s2: transpose (independent), then place_e after zeroing
    k_transpose_in<<<E / 32, tb, 0, s2>>>(x);
    cudaEventRecord(evT, s2);

    // s0: zero counters, then layer-1 place
    k_zero_both<<<(E + 255) / 256, 256>>>();
    cudaEventRecord(evZ, 0);

    cudaStreamWaitEvent(s2, evZ, 0);
    k_place_e<<<(NNZ + 255) / 256, 256, 0, s2>>>(w_out_rows, w_out_cols, v_out);
    cudaEventRecord(evE, s2);

    k_place_c<<<(NNZ + 255) / 256, 256>>>(w_in_rows, w_in_cols, v_in);

    // s0: gather_in after transpose; gather_out after place_e
    cudaStreamWaitEvent(0, evT, 0);
    k_gather_in_norm<<<NGROUPS, 256>>>(b_in, gamma, beta);
    cudaStreamWaitEvent(0, evE, 0);
    k_gather_out<<<E / 8, 256>>>(x, b_out, out);
}